// round 1
// baseline (speedup 1.0000x reference)
#include <cuda_runtime.h>

#define HH   512
#define NH   32
#define LL   8192
#define NLEV 13            // w^(2^k), k = 0..12
#define TSTEPS 128         // l-steps per lane (stride 32) -> warp covers 4096

// Scratch (device globals; no allocation allowed)
__device__ float2 g_Wp[HH * NLEV * NH];   // [h][k][n] : w^(2^k), ~1.7 MB (L2 resident)
__device__ float2 g_C2[HH * NH];          // 2 * C'  (factor 2 folded in)

// ---------------- f32x2 packed helpers ----------------
static __device__ __forceinline__ unsigned long long pk2(float lo, float hi) {
    unsigned long long r;
    asm("mov.b64 %0, {%1, %2};" : "=l"(r) : "f"(lo), "f"(hi));
    return r;
}
static __device__ __forceinline__ void upk2(unsigned long long v, float& lo, float& hi) {
    asm("mov.b64 {%0, %1}, %2;" : "=f"(lo), "=f"(hi) : "l"(v));
}
static __device__ __forceinline__ unsigned long long mul2(unsigned long long a, unsigned long long b) {
    unsigned long long d;
    asm("mul.rn.f32x2 %0, %1, %2;" : "=l"(d) : "l"(a), "l"(b));
    return d;
}
static __device__ __forceinline__ unsigned long long add2(unsigned long long a, unsigned long long b) {
    unsigned long long d;
    asm("add.rn.f32x2 %0, %1, %2;" : "=l"(d) : "l"(a), "l"(b));
    return d;
}
static __device__ __forceinline__ unsigned long long fma2(unsigned long long a, unsigned long long b,
                                                          unsigned long long c) {
    unsigned long long d;
    asm("fma.rn.f32x2 %0, %1, %2, %3;" : "=l"(d) : "l"(a), "l"(b), "l"(c));
    return d;
}

static __device__ __forceinline__ float2 cmulf(float2 a, float2 b) {
    float2 r;
    r.x = fmaf(a.x, b.x, -(a.y * b.y));
    r.y = fmaf(a.x, b.y,  (a.y * b.x));
    return r;
}

// ---------------- Setup: per (h,n) constants, fp64 power table ----------------
__global__ void s4d_setup(const float* __restrict__ Cr, const float* __restrict__ Ci,
                          const float* __restrict__ ldt, const float* __restrict__ lar,
                          const float* __restrict__ Aim) {
    int h = blockIdx.x;
    int n = threadIdx.x;
    int idx = h * NH + n;

    // Match reference fp32 discretization exactly for dtA
    float dtf  = expf(ldt[h]);
    float arf  = -expf(lar[idx]);
    float aif  = Aim[idx];
    float dtar = arf * dtf;
    float dtai = aif * dtf;

    // w = exp(dtA) in double, rounded to fp32 once
    double er = exp((double)dtar);
    double si, co;
    sincos((double)dtai, &si, &co);
    double wr = er * co;
    double wi = er * si;

    // C' = C * (w - 1) / A in fp32, mimicking the reference's rounding
    float wrf = (float)wr, wif = (float)wi;
    float nr = wrf - 1.0f, ni = wif;
    float den = arf * arf + aif * aif;
    float inv = 1.0f / den;
    float fr = (nr * arf + ni * aif) * inv;
    float fi = (ni * arf - nr * aif) * inv;
    float cr = Cr[idx], ci = Ci[idx];
    // fold the final *2 into C'
    g_C2[idx] = make_float2(2.0f * (cr * fr - ci * fi),
                            2.0f * (cr * fi + ci * fr));

    // Power table w^(2^k) via fp64 squaring (each stored level ~1 ulp accurate)
    double xr = wr, xi = wi;
    float2* dst = g_Wp + h * NLEV * NH + n;
    #pragma unroll
    for (int k = 0; k < NLEV; ++k) {
        dst[k * NH] = make_float2((float)xr, (float)xi);
        double tr = xr * xr - xi * xi;
        xi = 2.0 * xr * xi;
        xr = tr;
    }
}

// ---------------- Main: warp per (h, half-row), lane-interleaved l ----------------
__global__ void __launch_bounds__(32) s4d_main(float* __restrict__ out) {
    __shared__ float2 sWp[NLEV][NH];
    __shared__ float2 sC[NH];

    int h    = blockIdx.x >> 1;
    int half = blockIdx.x & 1;
    int lane = threadIdx.x;

    const float2* gw = g_Wp + h * NLEV * NH;
    #pragma unroll
    for (int i = lane; i < NLEV * NH; i += 32)
        (&sWp[0][0])[i] = gw[i];
    sC[lane] = g_C2[h * NH + lane];
    __syncwarp();

    // Per-thread state: 16 mode-pairs packed in f32x2
    unsigned long long pr[16], pi[16], wr[16], wi[16], nwi[16];

    #pragma unroll
    for (int j = 0; j < 16; ++j) {
        int m0 = 2 * j, m1 = 2 * j + 1;
        float2 pa = sC[m0];
        float2 pb = sC[m1];
        // p0 = C' * w^(half*4096 + lane) : only bits 0..4 and 12 can be set
        #pragma unroll
        for (int k = 0; k < 5; ++k) {
            if ((lane >> k) & 1) {
                pa = cmulf(pa, sWp[k][m0]);
                pb = cmulf(pb, sWp[k][m1]);
            }
        }
        if (half) {
            pa = cmulf(pa, sWp[12][m0]);
            pb = cmulf(pb, sWp[12][m1]);
        }
        pr[j] = pk2(pa.x, pb.x);
        pi[j] = pk2(pa.y, pb.y);
        float2 sa = sWp[5][m0];   // step multiplier w^32
        float2 sb = sWp[5][m1];
        wr[j]  = pk2(sa.x, sb.x);
        wi[j]  = pk2(sa.y, sb.y);
        nwi[j] = pk2(-sa.y, -sb.y);
    }

    float* op = out + h * LL + half * (LL / 2) + lane;

    #pragma unroll 4
    for (int t = 0; t < TSTEPS; ++t) {
        // K[l] = sum of real parts (tree reduction over 16 pairs)
        unsigned long long s8[8];
        #pragma unroll
        for (int j = 0; j < 8; ++j) s8[j] = add2(pr[2 * j], pr[2 * j + 1]);
        unsigned long long s4a = add2(s8[0], s8[1]);
        unsigned long long s4b = add2(s8[2], s8[3]);
        unsigned long long s4c = add2(s8[4], s8[5]);
        unsigned long long s4d = add2(s8[6], s8[7]);
        unsigned long long acc = add2(add2(s4a, s4b), add2(s4c, s4d));
        float lo, hi;
        upk2(acc, lo, hi);
        __stcs(op + t * 32, lo + hi);

        // p *= w^32  (packed complex multiply, 4 f32x2 ops per pair)
        #pragma unroll
        for (int j = 0; j < 16; ++j) {
            unsigned long long t1 = mul2(pi[j], nwi[j]);   // -pi*wi
            unsigned long long t2 = mul2(pr[j], wi[j]);    //  pr*wi
            unsigned long long npr = fma2(pr[j], wr[j], t1);
            pi[j] = fma2(pi[j], wr[j], t2);
            pr[j] = npr;
        }
    }
}

extern "C" void kernel_launch(void* const* d_in, const int* in_sizes, int n_in,
                              void* d_out, int out_size) {
    const float* C_real     = (const float*)d_in[0];
    const float* C_imag     = (const float*)d_in[1];
    const float* log_dt     = (const float*)d_in[2];
    const float* log_a_real = (const float*)d_in[3];
    const float* A_imag     = (const float*)d_in[4];
    // d_in[5] = L (compile-time constant LL here)
    float* out = (float*)d_out;

    s4d_setup<<<HH, NH>>>(C_real, C_imag, log_dt, log_a_real, A_imag);
    s4d_main<<<HH * 2, 32>>>(out);
}

// round 2
// speedup vs baseline: 1.0070x; 1.0070x over previous
#include <cuda_runtime.h>

#define HH   512
#define NH   32
#define LL   8192
#define NLEV 13            // w^(2^k), k = 0..12
#define TSTEPS 128         // l-steps per lane (stride 32) -> warp covers 4096

// Scratch (device globals; no allocation allowed)
__device__ float2 g_Wp[HH * NLEV * NH];   // [h][k][n] : w^(2^k), ~1.7 MB (L2 resident)
__device__ float2 g_C2[HH * NH];          // 2 * C'  (factor 2 folded in)

// ---------------- f32x2 packed helpers ----------------
static __device__ __forceinline__ unsigned long long pk2(float lo, float hi) {
    unsigned long long r;
    asm("mov.b64 %0, {%1, %2};" : "=l"(r) : "f"(lo), "f"(hi));
    return r;
}
static __device__ __forceinline__ void upk2(unsigned long long v, float& lo, float& hi) {
    asm("mov.b64 {%0, %1}, %2;" : "=f"(lo), "=f"(hi) : "l"(v));
}
static __device__ __forceinline__ unsigned long long mul2(unsigned long long a, unsigned long long b) {
    unsigned long long d;
    asm("mul.rn.f32x2 %0, %1, %2;" : "=l"(d) : "l"(a), "l"(b));
    return d;
}
static __device__ __forceinline__ unsigned long long add2(unsigned long long a, unsigned long long b) {
    unsigned long long d;
    asm("add.rn.f32x2 %0, %1, %2;" : "=l"(d) : "l"(a), "l"(b));
    return d;
}
static __device__ __forceinline__ unsigned long long fma2(unsigned long long a, unsigned long long b,
                                                          unsigned long long c) {
    unsigned long long d;
    asm("fma.rn.f32x2 %0, %1, %2, %3;" : "=l"(d) : "l"(a), "l"(b), "l"(c));
    return d;
}

static __device__ __forceinline__ float2 cmulf(float2 a, float2 b) {
    float2 r;
    r.x = fmaf(a.x, b.x, -(a.y * b.y));
    r.y = fmaf(a.x, b.y,  (a.y * b.x));
    return r;
}

// ---------------- Setup: per (h,n) constants, fp64 power table ----------------
__global__ void s4d_setup(const float* __restrict__ Cr, const float* __restrict__ Ci,
                          const float* __restrict__ ldt, const float* __restrict__ lar,
                          const float* __restrict__ Aim) {
    int h = blockIdx.x;
    int n = threadIdx.x;
    int idx = h * NH + n;

    // Match reference fp32 discretization exactly for dtA
    float dtf  = expf(ldt[h]);
    float arf  = -expf(lar[idx]);
    float aif  = Aim[idx];
    float dtar = arf * dtf;
    float dtai = aif * dtf;

    // w = exp(dtA) in double, rounded to fp32 once
    double er = exp((double)dtar);
    double si, co;
    sincos((double)dtai, &si, &co);
    double wr = er * co;
    double wi = er * si;

    // C' = C * (w - 1) / A in fp32, mimicking the reference's rounding
    float wrf = (float)wr, wif = (float)wi;
    float nr = wrf - 1.0f, ni = wif;
    float den = arf * arf + aif * aif;
    float inv = 1.0f / den;
    float fr = (nr * arf + ni * aif) * inv;
    float fi = (ni * arf - nr * aif) * inv;
    float cr = Cr[idx], ci = Ci[idx];
    // fold the final *2 into C'
    g_C2[idx] = make_float2(2.0f * (cr * fr - ci * fi),
                            2.0f * (cr * fi + ci * fr));

    // Power table w^(2^k) via fp64 squaring (each stored level ~1 ulp accurate)
    double xr = wr, xi = wi;
    float2* dst = g_Wp + h * NLEV * NH + n;
    #pragma unroll
    for (int k = 0; k < NLEV; ++k) {
        dst[k * NH] = make_float2((float)xr, (float)xi);
        double tr = xr * xr - xi * xi;
        xi = 2.0 * xr * xi;
        xr = tr;
    }
}

// ---------------- Main: warp per (h, half-row), lane-interleaved l ----------------
__global__ void __launch_bounds__(32) s4d_main(float* __restrict__ out) {
    __shared__ float2 sWp[NLEV][NH];
    __shared__ float2 sC[NH];

    int h    = blockIdx.x >> 1;
    int half = blockIdx.x & 1;
    int lane = threadIdx.x;

    const float2* gw = g_Wp + h * NLEV * NH;
    #pragma unroll
    for (int i = lane; i < NLEV * NH; i += 32)
        (&sWp[0][0])[i] = gw[i];
    sC[lane] = g_C2[h * NH + lane];
    __syncwarp();

    // Per-thread state: 16 mode-pairs packed in f32x2
    unsigned long long pr[16], pi[16], wr[16], wi[16], nwi[16];

    #pragma unroll
    for (int j = 0; j < 16; ++j) {
        int m0 = 2 * j, m1 = 2 * j + 1;
        float2 pa = sC[m0];
        float2 pb = sC[m1];
        // p0 = C' * w^(half*4096 + lane) : only bits 0..4 and 12 can be set
        #pragma unroll
        for (int k = 0; k < 5; ++k) {
            if ((lane >> k) & 1) {
                pa = cmulf(pa, sWp[k][m0]);
                pb = cmulf(pb, sWp[k][m1]);
            }
        }
        if (half) {
            pa = cmulf(pa, sWp[12][m0]);
            pb = cmulf(pb, sWp[12][m1]);
        }
        pr[j] = pk2(pa.x, pb.x);
        pi[j] = pk2(pa.y, pb.y);
        float2 sa = sWp[5][m0];   // step multiplier w^32
        float2 sb = sWp[5][m1];
        wr[j]  = pk2(sa.x, sb.x);
        wi[j]  = pk2(sa.y, sb.y);
        nwi[j] = pk2(-sa.y, -sb.y);
    }

    float* op = out + h * LL + half * (LL / 2) + lane;

    #pragma unroll 4
    for (int t = 0; t < TSTEPS; ++t) {
        // K[l] = sum of real parts (tree reduction over 16 pairs)
        unsigned long long s8[8];
        #pragma unroll
        for (int j = 0; j < 8; ++j) s8[j] = add2(pr[2 * j], pr[2 * j + 1]);
        unsigned long long s4a = add2(s8[0], s8[1]);
        unsigned long long s4b = add2(s8[2], s8[3]);
        unsigned long long s4c = add2(s8[4], s8[5]);
        unsigned long long s4d = add2(s8[6], s8[7]);
        unsigned long long acc = add2(add2(s4a, s4b), add2(s4c, s4d));
        float lo, hi;
        upk2(acc, lo, hi);
        __stcs(op + t * 32, lo + hi);

        // p *= w^32  (packed complex multiply, 4 f32x2 ops per pair)
        #pragma unroll
        for (int j = 0; j < 16; ++j) {
            unsigned long long t1 = mul2(pi[j], nwi[j]);   // -pi*wi
            unsigned long long t2 = mul2(pr[j], wi[j]);    //  pr*wi
            unsigned long long npr = fma2(pr[j], wr[j], t1);
            pi[j] = fma2(pi[j], wr[j], t2);
            pr[j] = npr;
        }
    }
}

extern "C" void kernel_launch(void* const* d_in, const int* in_sizes, int n_in,
                              void* d_out, int out_size) {
    const float* C_real     = (const float*)d_in[0];
    const float* C_imag     = (const float*)d_in[1];
    const float* log_dt     = (const float*)d_in[2];
    const float* log_a_real = (const float*)d_in[3];
    const float* A_imag     = (const float*)d_in[4];
    // d_in[5] = L (compile-time constant LL here)
    float* out = (float*)d_out;

    s4d_setup<<<HH, NH>>>(C_real, C_imag, log_dt, log_a_real, A_imag);
    s4d_main<<<HH * 2, 32>>>(out);
}

// round 3
// speedup vs baseline: 1.4091x; 1.3993x over previous
#include <cuda_runtime.h>

#define HH   512
#define NH   32
#define LL   8192
#define TSTEPS 128          // l-steps per lane (stride 32) -> warp covers 4096

// Per-(h,n) constant table, 10 float2 slots:
//   0..5 : w^(2^k), k=0..5   (slot 5 = w^32, the step multiplier)
//   6    : w^4096            (half-row jump)
//   7    : w^-32             (for the prev initial condition)
//   8    : C2 = 2*C*(w-1)/A  (factor 2 folded in)
//   9    : (T, -Q) = (2*Re(w^32), -|w^32|^2)
#define SLOTS 10
__device__ float2 g_tab[HH * SLOTS * NH];

// ---------------- f32x2 packed helpers ----------------
static __device__ __forceinline__ unsigned long long pk2(float lo, float hi) {
    unsigned long long r;
    asm("mov.b64 %0, {%1, %2};" : "=l"(r) : "f"(lo), "f"(hi));
    return r;
}
static __device__ __forceinline__ void upk2(unsigned long long v, float& lo, float& hi) {
    asm("mov.b64 {%0, %1}, %2;" : "=f"(lo), "=f"(hi) : "l"(v));
}
static __device__ __forceinline__ unsigned long long mul2(unsigned long long a, unsigned long long b) {
    unsigned long long d;
    asm("mul.rn.f32x2 %0, %1, %2;" : "=l"(d) : "l"(a), "l"(b));
    return d;
}
static __device__ __forceinline__ unsigned long long add2(unsigned long long a, unsigned long long b) {
    unsigned long long d;
    asm("add.rn.f32x2 %0, %1, %2;" : "=l"(d) : "l"(a), "l"(b));
    return d;
}
static __device__ __forceinline__ unsigned long long fma2(unsigned long long a, unsigned long long b,
                                                          unsigned long long c) {
    unsigned long long d;
    asm("fma.rn.f32x2 %0, %1, %2, %3;" : "=l"(d) : "l"(a), "l"(b), "l"(c));
    return d;
}

static __device__ __forceinline__ float2 cmulf(float2 a, float2 b) {
    float2 r;
    r.x = fmaf(a.x, b.x, -(a.y * b.y));
    r.y = fmaf(a.x, b.y,  (a.y * b.x));
    return r;
}

// ---------------- Setup: fp32 except one double sincos for the 4096-jump phase ----------------
__global__ void s4d_setup(const float* __restrict__ Cr, const float* __restrict__ Ci,
                          const float* __restrict__ ldt, const float* __restrict__ lar,
                          const float* __restrict__ Aim) {
    int idx = blockIdx.x * blockDim.x + threadIdx.x;   // (h,n) flat
    if (idx >= HH * NH) return;
    int h = idx >> 5;
    int n = idx & 31;

    // fp32 discretization, matching reference rounding
    float dtf  = expf(ldt[h]);
    float arf  = -expf(lar[idx]);
    float aif  = Aim[idx];
    float dtar = arf * dtf;
    float dtai = aif * dtf;

    // base w = exp(dtA), fp32 (same as reference's complex64 exp)
    float er, si, co;
    er = expf(dtar);
    sincosf(dtai, &si, &co);
    float2 w = make_float2(er * co, er * si);

    // C2 = 2 * C * (w - 1) / A, fp32 like the reference
    float nr = w.x - 1.0f, ni = w.y;
    float den = arf * arf + aif * aif;
    float inv = 1.0f / den;
    float fr = (nr * arf + ni * aif) * inv;
    float fi = (ni * arf - nr * aif) * inv;
    float cr = Cr[idx], ci = Ci[idx];
    float2 C2 = make_float2(2.0f * (cr * fr - ci * fi),
                            2.0f * (cr * fi + ci * fr));

    float2* dst = g_tab + (h * SLOTS) * NH + n;        // [h][slot][n]

    // levels 0..5 by fp32 squaring
    float2 x = w;
    #pragma unroll
    for (int k = 0; k < 6; ++k) {
        dst[k * NH] = x;
        float tr = fmaf(x.x, x.x, -(x.y * x.y));
        x.y = 2.0f * x.x * x.y;
        x.x = tr;
    }
    float2 w32 = dst[5 * NH];  // just computed above loop stored; reload not needed:
    // (x now holds w^64; w32 was stored at k=5)
    // recompute w32 locally (avoid smem/global reload): redo loop capture
    // -- simpler: rebuild via the stored value
    w32 = make_float2(0.f, 0.f);
    {
        float2 y = w;
        #pragma unroll
        for (int k = 0; k < 5; ++k) {
            float tr = fmaf(y.x, y.x, -(y.y * y.y));
            y.y = 2.0f * y.x * y.y;
            y.x = tr;
        }
        w32 = y;
    }

    // slot 6: w^4096 — phase needs fp64 range reduction; dtai*4096 is exact in fp32
    {
        double th = (double)dtai * 4096.0;
        double s, c;
        sincos(th, &s, &c);
        float mag = expf(dtar * 4096.0f);   // underflow to 0 == true answer
        dst[6 * NH] = make_float2(mag * (float)c, mag * (float)s);
    }

    // slot 7: w^-32 = conj(w32)/|w32|^2
    float q = fmaf(w32.x, w32.x, w32.y * w32.y);
    float qi = 1.0f / q;
    dst[7 * NH] = make_float2(w32.x * qi, -w32.y * qi);

    // slot 8: C2
    dst[8 * NH] = C2;

    // slot 9: (T, -Q)
    dst[9 * NH] = make_float2(2.0f * w32.x, -q);
}

// ---------------- Main: warp per (h, half-row); 2-term real recurrence ----------------
__global__ void __launch_bounds__(32) s4d_main(float* __restrict__ out) {
    __shared__ float2 st[SLOTS][NH];

    int h    = blockIdx.x >> 1;
    int half = blockIdx.x & 1;
    int lane = threadIdx.x;

    const float2* gt = g_tab + (h * SLOTS) * NH;
    #pragma unroll
    for (int i = lane; i < SLOTS * NH; i += 32)
        (&st[0][0])[i] = gt[i];
    __syncwarp();

    // Per-thread state: 16 mode-pairs packed in f32x2
    unsigned long long cur[16], prv[16], T2[16], Qn[16];

    #pragma unroll
    for (int j = 0; j < 16; ++j) {
        int m0 = 2 * j, m1 = 2 * j + 1;
        float2 pa = st[8][m0];
        float2 pb = st[8][m1];
        // p0 = C2 * w^(half*4096 + lane) : bits 0..4 of lane, plus the 4096 jump
        #pragma unroll
        for (int k = 0; k < 5; ++k) {
            if ((lane >> k) & 1) {
                pa = cmulf(pa, st[k][m0]);
                pb = cmulf(pb, st[k][m1]);
            }
        }
        if (half) {
            pa = cmulf(pa, st[6][m0]);
            pb = cmulf(pb, st[6][m1]);
        }
        // prev = p0 * w^-32  (valid also for negative exponents)
        float2 qa = cmulf(pa, st[7][m0]);
        float2 qb = cmulf(pb, st[7][m1]);

        cur[j] = pk2(pa.x, pb.x);
        prv[j] = pk2(qa.x, qb.x);
        float2 ta = st[9][m0];
        float2 tb = st[9][m1];
        T2[j] = pk2(ta.x, tb.x);   //  T  = 2 Re(w^32)
        Qn[j] = pk2(ta.y, tb.y);   // -Q  = -|w^32|^2
    }

    float* op = out + h * LL + half * (LL / 2) + lane;

    #pragma unroll 2
    for (int t = 0; t < TSTEPS; t += 2) {
        // ---- emit sum(cur) at l = t ----
        {
            unsigned long long s8[8];
            #pragma unroll
            for (int j = 0; j < 8; ++j) s8[j] = add2(cur[2 * j], cur[2 * j + 1]);
            unsigned long long s4a = add2(s8[0], s8[1]);
            unsigned long long s4b = add2(s8[2], s8[3]);
            unsigned long long s4c = add2(s8[4], s8[5]);
            unsigned long long s4d = add2(s8[6], s8[7]);
            unsigned long long acc = add2(add2(s4a, s4b), add2(s4c, s4d));
            float lo, hi;
            upk2(acc, lo, hi);
            __stcs(op + t * 32, lo + hi);
        }
        // advance: prv <- T*cur - Q*prv  (prv now holds x_{t+1})
        #pragma unroll
        for (int j = 0; j < 16; ++j)
            prv[j] = fma2(T2[j], cur[j], mul2(Qn[j], prv[j]));

        // ---- emit sum(prv) at l = t+1 ----
        {
            unsigned long long s8[8];
            #pragma unroll
            for (int j = 0; j < 8; ++j) s8[j] = add2(prv[2 * j], prv[2 * j + 1]);
            unsigned long long s4a = add2(s8[0], s8[1]);
            unsigned long long s4b = add2(s8[2], s8[3]);
            unsigned long long s4c = add2(s8[4], s8[5]);
            unsigned long long s4d = add2(s8[6], s8[7]);
            unsigned long long acc = add2(add2(s4a, s4b), add2(s4c, s4d));
            float lo, hi;
            upk2(acc, lo, hi);
            __stcs(op + (t + 1) * 32, lo + hi);
        }
        // advance: cur <- T*prv - Q*cur  (cur now holds x_{t+2})
        #pragma unroll
        for (int j = 0; j < 16; ++j)
            cur[j] = fma2(T2[j], prv[j], mul2(Qn[j], cur[j]));
    }
}

extern "C" void kernel_launch(void* const* d_in, const int* in_sizes, int n_in,
                              void* d_out, int out_size) {
    const float* C_real     = (const float*)d_in[0];
    const float* C_imag     = (const float*)d_in[1];
    const float* log_dt     = (const float*)d_in[2];
    const float* log_a_real = (const float*)d_in[3];
    const float* A_imag     = (const float*)d_in[4];
    float* out = (float*)d_out;

    s4d_setup<<<(HH * NH + 255) / 256, 256>>>(C_real, C_imag, log_dt, log_a_real, A_imag);
    s4d_main<<<HH * 2, 32>>>(out);
}